// round 7
// baseline (speedup 1.0000x reference)
#include <cuda_runtime.h>

#define BB 32
#define NN 2048
#define EPSF 5e-4f
#define HH 5.0f

__device__ float g_Fp[BB*8*32];    // node partials: [row][blk8][node]
__device__ float g_inv[BB];        // 1/max(maxDCG,EPS)
__device__ float g_part[BB*4];     // per-(row,chunk) numer*inv partials

// ---------------------------------------------------------------------------
// K1, grid (9, BB) x 512:
//  blk<8 : node partial sums over 128 score-pairs (8 paired sigmoids/thread)
//          sig(a)+sig(b) vs node W: (2ab+pW)/(W^2+pW+ab), p=a+b precomputed.
//  blk==8: label histogram -> rank boundaries -> maxDCG -> g_inv[b].
// ---------------------------------------------------------------------------
__global__ __launch_bounds__(512, 2)
void k1(const float* __restrict__ yp, const float* __restrict__ yt) {
    int blk = blockIdx.x, b = blockIdx.y;
    int t = threadIdx.x, w = t >> 5, lane = t & 31;

    if (blk < 8) {
        __shared__ float2 sP[128];
        __shared__ float sF[16*33];
        if (t < 128) {
            float2 sc = ((const float2*)(yp + b*NN + blk*256))[t];
            float ea = __expf(sc.x), eb = __expf(sc.y);
            sP[t] = make_float2(ea + eb, 2.f*ea*eb);
        }
        // lane = Chebyshev-Gauss node k: x_k = HH*cos(pi(2k+1)/64)
        float W  = __expf(HH * cospif((float)(2*lane + 1) * (1.0f/64.0f)));
        float W2 = W * W;
        __syncthreads();

        const float4* P4 = (const float4*)sP;     // (p0,r2_0,p1,r2_1)
        float acc = 0.f;
        #pragma unroll
        for (int i = 0; i < 4; i++) {
            float4 q = P4[w*4 + i];
            float h0 = fmaf(0.5f, q.y, W2);
            float d0 = fmaf(q.x, W, h0);
            float n0 = fmaf(q.x, W, q.y);
            acc = fmaf(n0, __frcp_rn(d0), acc);
            float h1 = fmaf(0.5f, q.w, W2);
            float d1 = fmaf(q.z, W, h1);
            float n1 = fmaf(q.z, W, q.w);
            acc = fmaf(n1, __frcp_rn(d1), acc);
        }
        sF[w*33 + lane] = acc;
        __syncthreads();
        if (w == 0) {
            float F = 0.f;
            #pragma unroll
            for (int i = 0; i < 16; i++) F += sF[i*33 + lane];
            g_Fp[(b*8 + blk)*32 + lane] = F;
        }
    } else {
        __shared__ unsigned long long sH[16];
        __shared__ int sOff[4];
        __shared__ float sR[16];
        float4 lb = ((const float4*)(yt + b*NN))[t];      // 4 labels/thread
        int v0 = (int)lb.x, v1 = (int)lb.y, v2 = (int)lb.z, v3 = (int)lb.w;
        unsigned long long pk = (1ULL << (12*v0)) + (1ULL << (12*v1))
                              + (1ULL << (12*v2)) + (1ULL << (12*v3));
        #pragma unroll
        for (int o = 16; o; o >>= 1) pk += __shfl_xor_sync(0xffffffffu, pk, o);
        if (lane == 0) sH[w] = pk;
        __syncthreads();
        if (w == 0) {
            unsigned long long hh = (lane < 16) ? sH[lane] : 0ULL;
            #pragma unroll
            for (int o = 8; o; o >>= 1) hh += __shfl_xor_sync(0xffffffffu, hh, o);
            if (lane == 0) {
                int c4 = (int)((hh >> 48) & 0xFFF);
                int c3 = (int)((hh >> 36) & 0xFFF);
                int c2 = (int)((hh >> 24) & 0xFFF);
                int c1 = (int)((hh >> 12) & 0xFFF);
                sOff[0] = c4;                  // ranks [0,B4)   -> label 4
                sOff[1] = c4 + c3;             // [B4,B3)        -> 3
                sOff[2] = c4 + c3 + c2;        // [B3,B2)        -> 2
                sOff[3] = c4 + c3 + c2 + c1;   // [B2,B1)->1 else 0
            }
        }
        __syncthreads();
        int B4 = sOff[0], B3 = sOff[1], B2 = sOff[2], B1 = sOff[3];
        float mdcg = 0.f;
        #pragma unroll
        for (int i = 0; i < 4; i++) {
            int n = t + i*512;                  // rank r = n (0-based)
            int vr = 4 - (n >= B4) - (n >= B3) - (n >= B2) - (n >= B1);
            float g2 = (float)((1 << vr) - 1);
            mdcg += __fdividef(g2, __log2f((float)(n + 2)));
        }
        #pragma unroll
        for (int o = 16; o; o >>= 1) mdcg += __shfl_xor_sync(0xffffffffu, mdcg, o);
        if (lane == 0) sR[w] = mdcg;
        __syncthreads();
        if (w == 0) {
            float x = (lane < 16) ? sR[lane] : 0.f;
            #pragma unroll
            for (int o = 8; o; o >>= 1) x += __shfl_xor_sync(0xffffffffu, x, o);
            if (lane == 0) g_inv[b] = 1.0f / fmaxf(x, EPSF);
        }
    }
}

// ---------------------------------------------------------------------------
// K2, grid (4, BB) x 512: fold node partials, warp-parallel DCT-II (2 coefs
// per warp), Clenshaw at 1 point/thread, block partial * invMaxDCG -> g_part.
// ---------------------------------------------------------------------------
__global__ __launch_bounds__(512, 2)
void k2(const float* __restrict__ yp, const float* __restrict__ yt) {
    int c = blockIdx.x, b = blockIdx.y;
    int t = threadIdx.x, w = t >> 5, lane = t & 31;
    __shared__ float sFp[256];
    __shared__ float sFn[32];
    __shared__ float sCoef[32];
    __shared__ float sR[16];

    int n = c*512 + t;
    float s = yp[b*NN + n];                    // issue DRAM loads up front
    int v = (int)yt[b*NN + n];
    float inv = g_inv[b];
    if (t < 256) sFp[t] = g_Fp[b*256 + t];
    __syncthreads();

    if (t < 32) {
        float F = 0.f;
        #pragma unroll
        for (int i = 0; i < 8; i++) F += sFp[i*32 + t];
        sFn[t] = F;
    }
    __syncthreads();

    // DCT-II: c_m = (2/32) sum_k F_k cos(pi m(2k+1)/64); c_0 halved.
    float fk = sFn[lane];
    #pragma unroll
    for (int j = 0; j < 2; j++) {
        int m = w + 16*j;
        float term = fk * cospif((float)(m*(2*lane + 1)) * (1.0f/64.0f));
        #pragma unroll
        for (int o = 16; o; o >>= 1) term += __shfl_xor_sync(0xffffffffu, term, o);
        if (lane == 0) {
            float cc = term * (2.0f/32.0f);
            if (m == 0) cc *= 0.5f;
            sCoef[m] = cc;
        }
    }
    __syncthreads();

    float u = fminf(fmaxf(s * (1.0f/HH), -1.f), 1.f);
    float tu = u + u, y1 = 0.f, y2 = 0.f;
    #pragma unroll
    for (int m = 31; m >= 1; m--) {
        float tmp = fmaf(tu, y1, sCoef[m]) - y2;
        y2 = y1; y1 = tmp;
    }
    float F = fmaf(u, y1, sCoef[0]) - y2;               // interpolated F(s)
    float gain = (float)((1 << v) - 1);
    float numer = __fdividef(gain, __log2f(1.5f + F)) * inv;  // pos = 0.5+F

    #pragma unroll
    for (int o = 16; o; o >>= 1) numer += __shfl_xor_sync(0xffffffffu, numer, o);
    if (lane == 0) sR[w] = numer;
    __syncthreads();
    if (w == 0) {
        float x = (lane < 16) ? sR[lane] : 0.f;
        #pragma unroll
        for (int o = 8; o; o >>= 1) x += __shfl_xor_sync(0xffffffffu, x, o);
        if (lane == 0) g_part[b*4 + c] = x;
    }
}

// K3: mean of 128 partials
__global__ void k3(float* __restrict__ out) {
    int t = threadIdx.x, w = t >> 5, lane = t & 31;  // 128 threads
    __shared__ float sR[4];
    float x = g_part[t];
    #pragma unroll
    for (int o = 16; o; o >>= 1) x += __shfl_xor_sync(0xffffffffu, x, o);
    if (lane == 0) sR[w] = x;
    __syncthreads();
    if (t == 0) out[0] = (sR[0] + sR[1] + sR[2] + sR[3]) * (1.0f/BB);
}

extern "C" void kernel_launch(void* const* d_in, const int* in_sizes, int n_in,
                              void* d_out, int out_size) {
    const float* yp = (const float*)d_in[0];
    const float* yt = (const float*)d_in[1];
    float* out = (float*)d_out;
    (void)in_sizes; (void)n_in; (void)out_size;

    dim3 g1(9, BB);
    k1<<<g1, 512>>>(yp, yt);
    dim3 g2(4, BB);
    k2<<<g2, 512>>>(yp, yt);
    k3<<<1, 128>>>(out);
}